// round 10
// baseline (speedup 1.0000x reference)
#include <cuda_runtime.h>
#include <math.h>

#define PH 11
#define PW 11
#define SCALEF 0.0625f
#define FH 200
#define FW 200
#define NC 256
#define CH_STRIDE (FH * FW)   // 40000 elements (160000 B, fits LDG imm offset)
#define CPW 8
#define WARPS 8               // 8 warps x 8 ch = 64 channels per block

struct RowInfo { int off; float ly; };   // 8B -> single LDS.64

// Block = one roi x 64 channels; warp = 8 channels; lanes 0..21 = 22 x-samples
// (px = lane>>1, sx = lane&1; lanes >=22 mirror sample 21 -> broadcast loads).
// Register cache holds X-INTERPOLATED rowA/rowB per channel (2 regs/ch).
// Monotone row reuse: off==cOff full reuse, off==cOff+FW shift B->A + load
// rowB only, else load both. Loads grouped 4 channels at a time to cap live
// registers; __launch_bounds__(256,5) targets <=51 regs so occupancy reaches
// ~60% (measured: CPW=8 at regs=59/occ=44% was latency-bound, issue only 58%).
__global__ __launch_bounds__(256, 5) void roialign_maxpool_kernel(
    const float* __restrict__ feat,
    const float* __restrict__ rois,
    float* __restrict__ out)
{
    __shared__ RowInfo s_row[2 * PH];
    __shared__ float pooled[WARPS][CPW][PH][PW];

    const int k    = blockIdx.x;
    const int tid  = threadIdx.x;
    const int warp = tid >> 5;
    const int lane = tid & 31;
    const unsigned FULL = 0xffffffffu;

    const float x1 = __ldg(&rois[k * 5 + 1]) * SCALEF;
    const float y1 = __ldg(&rois[k * 5 + 2]) * SCALEF;
    const float x2 = __ldg(&rois[k * 5 + 3]) * SCALEF;
    const float y2 = __ldg(&rois[k * 5 + 4]) * SCALEF;
    const int   b  = (int)__ldg(&rois[k * 5 + 0]);

    const float bin_w = fmaxf(x2 - x1, 1.0f) * (1.0f / PW);
    const float bin_h = fmaxf(y2 - y1, 1.0f) * (1.0f / PH);

    // 22 y-sample rows once per block (input ranges guarantee no clamping)
    if (tid < 2 * PH) {
        float yc  = y1 + ((float)tid * 0.5f + 0.25f) * bin_h;
        int   ylo = (int)floorf(yc);
        s_row[tid].off = ylo * FW;
        s_row[tid].ly  = yc - (float)ylo;
    }

    // Per-lane x geometry
    const int  l  = min(lane, 2 * PW - 1);
    const int  px = l >> 1;
    const int  sx = l & 1;
    const bool store_lane = (lane < 2 * PW) && (sx == 0);

    float xc = x1 + ((float)px + 0.25f + 0.5f * (float)sx) * bin_w;
    const int   xlo = (int)floorf(xc);
    const float lx  = xc - (float)xlo;
    const float hx  = 1.0f - lx;

    const int c0 = blockIdx.y * (WARPS * CPW) + warp * CPW;
    const float* __restrict__ fbase =
        feat + ((size_t)(b * NC + c0)) * CH_STRIDE + xlo;

    __syncthreads();

    // X-interpolated row cache per channel
    float rA[CPW], rB[CPW];
    int   cOff = -0x40000000;

    for (int py = 0; py < PH; ++py) {
        float a[CPW];

        // ---- sample row t = 2*py ----
        {
            const RowInfo ri = s_row[2 * py];
            const int off = ri.off;
            if (off != cOff) {                      // warp-uniform
                const float* __restrict__ p = fbase + off;
                if (off == cOff + FW) {
#pragma unroll
                    for (int j = 0; j < CPW; ++j) rA[j] = rB[j];
                } else {
                    // grouped 4-channel load batches cap live registers
#pragma unroll
                    for (int g = 0; g < CPW; g += 4) {
                        float lo0 = __ldg(p + (g + 0) * CH_STRIDE);
                        float hi0 = __ldg(p + (g + 0) * CH_STRIDE + 1);
                        float lo1 = __ldg(p + (g + 1) * CH_STRIDE);
                        float hi1 = __ldg(p + (g + 1) * CH_STRIDE + 1);
                        float lo2 = __ldg(p + (g + 2) * CH_STRIDE);
                        float hi2 = __ldg(p + (g + 2) * CH_STRIDE + 1);
                        float lo3 = __ldg(p + (g + 3) * CH_STRIDE);
                        float hi3 = __ldg(p + (g + 3) * CH_STRIDE + 1);
                        rA[g + 0] = fmaf(lx, hi0, hx * lo0);
                        rA[g + 1] = fmaf(lx, hi1, hx * lo1);
                        rA[g + 2] = fmaf(lx, hi2, hx * lo2);
                        rA[g + 3] = fmaf(lx, hi3, hx * lo3);
                    }
                }
#pragma unroll
                for (int g = 0; g < CPW; g += 4) {
                    float lo0 = __ldg(p + (g + 0) * CH_STRIDE + FW);
                    float hi0 = __ldg(p + (g + 0) * CH_STRIDE + FW + 1);
                    float lo1 = __ldg(p + (g + 1) * CH_STRIDE + FW);
                    float hi1 = __ldg(p + (g + 1) * CH_STRIDE + FW + 1);
                    float lo2 = __ldg(p + (g + 2) * CH_STRIDE + FW);
                    float hi2 = __ldg(p + (g + 2) * CH_STRIDE + FW + 1);
                    float lo3 = __ldg(p + (g + 3) * CH_STRIDE + FW);
                    float hi3 = __ldg(p + (g + 3) * CH_STRIDE + FW + 1);
                    rB[g + 0] = fmaf(lx, hi0, hx * lo0);
                    rB[g + 1] = fmaf(lx, hi1, hx * lo1);
                    rB[g + 2] = fmaf(lx, hi2, hx * lo2);
                    rB[g + 3] = fmaf(lx, hi3, hx * lo3);
                }
                cOff = off;
            }
#pragma unroll
            for (int j = 0; j < CPW; ++j)
                a[j] = fmaf(ri.ly, rB[j] - rA[j], rA[j]);
        }

        // ---- sample row t = 2*py + 1 ----
        {
            const RowInfo ri = s_row[2 * py + 1];
            const int off = ri.off;
            if (off != cOff) {                      // warp-uniform
                const float* __restrict__ p = fbase + off;
                if (off == cOff + FW) {
#pragma unroll
                    for (int j = 0; j < CPW; ++j) rA[j] = rB[j];
                } else {
#pragma unroll
                    for (int g = 0; g < CPW; g += 4) {
                        float lo0 = __ldg(p + (g + 0) * CH_STRIDE);
                        float hi0 = __ldg(p + (g + 0) * CH_STRIDE + 1);
                        float lo1 = __ldg(p + (g + 1) * CH_STRIDE);
                        float hi1 = __ldg(p + (g + 1) * CH_STRIDE + 1);
                        float lo2 = __ldg(p + (g + 2) * CH_STRIDE);
                        float hi2 = __ldg(p + (g + 2) * CH_STRIDE + 1);
                        float lo3 = __ldg(p + (g + 3) * CH_STRIDE);
                        float hi3 = __ldg(p + (g + 3) * CH_STRIDE + 1);
                        rA[g + 0] = fmaf(lx, hi0, hx * lo0);
                        rA[g + 1] = fmaf(lx, hi1, hx * lo1);
                        rA[g + 2] = fmaf(lx, hi2, hx * lo2);
                        rA[g + 3] = fmaf(lx, hi3, hx * lo3);
                    }
                }
#pragma unroll
                for (int g = 0; g < CPW; g += 4) {
                    float lo0 = __ldg(p + (g + 0) * CH_STRIDE + FW);
                    float hi0 = __ldg(p + (g + 0) * CH_STRIDE + FW + 1);
                    float lo1 = __ldg(p + (g + 1) * CH_STRIDE + FW);
                    float hi1 = __ldg(p + (g + 1) * CH_STRIDE + FW + 1);
                    float lo2 = __ldg(p + (g + 2) * CH_STRIDE + FW);
                    float hi2 = __ldg(p + (g + 2) * CH_STRIDE + FW + 1);
                    float lo3 = __ldg(p + (g + 3) * CH_STRIDE + FW);
                    float hi3 = __ldg(p + (g + 3) * CH_STRIDE + FW + 1);
                    rB[g + 0] = fmaf(lx, hi0, hx * lo0);
                    rB[g + 1] = fmaf(lx, hi1, hx * lo1);
                    rB[g + 2] = fmaf(lx, hi2, hx * lo2);
                    rB[g + 3] = fmaf(lx, hi3, hx * lo3);
                }
                cOff = off;
            }
#pragma unroll
            for (int j = 0; j < CPW; ++j)
                a[j] += fmaf(ri.ly, rB[j] - rA[j], rA[j]);
        }

        // fold sx pair; even lanes hold the 2x2-sample mean
#pragma unroll
        for (int j = 0; j < CPW; ++j)
            a[j] += __shfl_xor_sync(FULL, a[j], 1);
        if (store_lane) {
#pragma unroll
            for (int j = 0; j < CPW; ++j)
                pooled[warp][j][py][px] = a[j] * 0.25f;
        }
    }
    __syncwarp();

    // 3x3 stride-2 maxpool over each 11x11 pooled tile -> 5x5
    if (lane < 25) {
        const int oy = lane / 5;
        const int ox = lane % 5;
#pragma unroll
        for (int j = 0; j < CPW; ++j) {
            float m = -INFINITY;
#pragma unroll
            for (int dy = 0; dy < 3; ++dy)
#pragma unroll
                for (int dx = 0; dx < 3; ++dx)
                    m = fmaxf(m, pooled[warp][j][2 * oy + dy][2 * ox + dx]);
            out[(((size_t)k * NC + (c0 + j)) * 5 + oy) * 5 + ox] = m;
        }
    }
}

extern "C" void kernel_launch(void* const* d_in, const int* in_sizes, int n_in,
                              void* d_out, int out_size)
{
    const float* feat = (const float*)d_in[0];
    const float* rois = (const float*)d_in[1];
    float* out = (float*)d_out;

    const int K = in_sizes[1] / 5;  // 512 rois

    dim3 grid(K, NC / (WARPS * CPW));   // (512, 4)
    dim3 block(256);
    roialign_maxpool_kernel<<<grid, block>>>(feat, rois, out);
}

// round 11
// speedup vs baseline: 1.2004x; 1.2004x over previous
#include <cuda_runtime.h>
#include <math.h>

#define PH 11
#define PW 11
#define SCALEF 0.0625f
#define FH 200
#define FW 200
#define NC 256
#define CH_STRIDE (FH * FW)   // 40000 elements (160000 B, fits LDG imm offset)
#define CPW 4
#define WARPS 8

struct RowInfo { int off; float ly; };   // 8B -> single LDS.64

// Block = one roi x 32 channels; warp = 4 channels; lanes 0..21 = 22 x-samples
// (px = lane>>1, sx = lane&1; lanes >=22 mirror sample 21 -> broadcast loads).
// DUAL row cache per channel: (A0,B0) = x-interp rows for sample row 2*py,
// (A1,B1) for 2*py+1. Both row-update load batches of a bin issue back-to-back
// at iteration top (branches resolve from fast LDS), halving scoreboard stalls
// vs the single-cache version. Monotone reuse chain unchanged:
//   o0 vs prev o1: equal -> copy; +FW -> shift B1->A0, load B0; else load both
//   o1 vs o0:      equal -> copy; +FW -> shift B0->A1, load B1; else load both
// Input ranges guarantee no boundary clamp (x<=193.75<199, y likewise).
__global__ __launch_bounds__(256) void roialign_maxpool_kernel(
    const float* __restrict__ feat,
    const float* __restrict__ rois,
    float* __restrict__ out)
{
    __shared__ RowInfo s_row[2 * PH];
    __shared__ float pooled[WARPS][CPW][PH][PW];

    const int k    = blockIdx.x;
    const int tid  = threadIdx.x;
    const int warp = tid >> 5;
    const int lane = tid & 31;
    const unsigned FULL = 0xffffffffu;

    const float x1 = __ldg(&rois[k * 5 + 1]) * SCALEF;
    const float y1 = __ldg(&rois[k * 5 + 2]) * SCALEF;
    const float x2 = __ldg(&rois[k * 5 + 3]) * SCALEF;
    const float y2 = __ldg(&rois[k * 5 + 4]) * SCALEF;
    const int   b  = (int)__ldg(&rois[k * 5 + 0]);

    const float bin_w = fmaxf(x2 - x1, 1.0f) * (1.0f / PW);
    const float bin_h = fmaxf(y2 - y1, 1.0f) * (1.0f / PH);

    // 22 y-sample rows once per block
    if (tid < 2 * PH) {
        float yc  = y1 + ((float)tid * 0.5f + 0.25f) * bin_h;
        int   ylo = (int)floorf(yc);
        s_row[tid].off = ylo * FW;
        s_row[tid].ly  = yc - (float)ylo;
    }

    // Per-lane x geometry
    const int  l  = min(lane, 2 * PW - 1);
    const int  px = l >> 1;
    const int  sx = l & 1;
    const bool store_lane = (lane < 2 * PW) && (sx == 0);

    float xc = x1 + ((float)px + 0.25f + 0.5f * (float)sx) * bin_w;
    const int   xlo = (int)floorf(xc);
    const float lx  = xc - (float)xlo;
    const float hx  = 1.0f - lx;

    const int c0 = blockIdx.y * (WARPS * CPW) + warp * CPW;
    const float* __restrict__ fbase =
        feat + ((size_t)(b * NC + c0)) * CH_STRIDE + xlo;

    __syncthreads();

    // Dual x-interpolated row cache
    float A0[CPW], B0[CPW], A1[CPW], B1[CPW];
    int   p1 = -0x40000000;    // row offset cached in (A1, B1)

#define LOADROW(DST, POFF)                                                     \
    {                                                                          \
        const float* __restrict__ _p = fbase + (POFF);                         \
        DST[0] = fmaf(lx, __ldg(_p + 0 * CH_STRIDE + 1), hx * __ldg(_p + 0 * CH_STRIDE)); \
        DST[1] = fmaf(lx, __ldg(_p + 1 * CH_STRIDE + 1), hx * __ldg(_p + 1 * CH_STRIDE)); \
        DST[2] = fmaf(lx, __ldg(_p + 2 * CH_STRIDE + 1), hx * __ldg(_p + 2 * CH_STRIDE)); \
        DST[3] = fmaf(lx, __ldg(_p + 3 * CH_STRIDE + 1), hx * __ldg(_p + 3 * CH_STRIDE)); \
    }
#define COPYROW(DST, SRC)                                                      \
    { DST[0] = SRC[0]; DST[1] = SRC[1]; DST[2] = SRC[2]; DST[3] = SRC[3]; }

    for (int py = 0; py < PH; ++py) {
        const RowInfo i0 = s_row[2 * py];
        const RowInfo i1 = s_row[2 * py + 1];
        const int o0 = i0.off;
        const int o1 = i1.off;

        // establish (A0,B0) = rows (o0, o0+FW) from previous (A1,B1)=(p1,p1+FW)
        if (o0 == p1) {
            COPYROW(A0, A1) COPYROW(B0, B1)
        } else if (o0 == p1 + FW) {
            COPYROW(A0, B1) LOADROW(B0, o0 + FW)
        } else {
            LOADROW(A0, o0) LOADROW(B0, o0 + FW)
        }
        // establish (A1,B1) = rows (o1, o1+FW)
        if (o1 == o0) {
            COPYROW(A1, A0) COPYROW(B1, B0)
        } else if (o1 == o0 + FW) {
            COPYROW(A1, B0) LOADROW(B1, o1 + FW)
        } else {
            LOADROW(A1, o1) LOADROW(B1, o1 + FW)
        }
        p1 = o1;

        // both y-interps together; a = sum of the two sample rows
        float a[CPW];
#pragma unroll
        for (int j = 0; j < CPW; ++j) {
            float v0 = fmaf(i0.ly, B0[j] - A0[j], A0[j]);
            float v1 = fmaf(i1.ly, B1[j] - A1[j], A1[j]);
            a[j] = v0 + v1;
        }

        // fold sx pair; even lanes hold the bin sum (scale folded in epilogue)
#pragma unroll
        for (int j = 0; j < CPW; ++j)
            a[j] += __shfl_xor_sync(FULL, a[j], 1);
        if (store_lane) {
#pragma unroll
            for (int j = 0; j < CPW; ++j)
                pooled[warp][j][py][px] = a[j];
        }
    }
    __syncwarp();

    // 3x3 stride-2 maxpool over each 11x11 tile -> 5x5 (x0.25 folded here)
    if (lane < 25) {
        const int oy = lane / 5;
        const int ox = lane % 5;
#pragma unroll
        for (int j = 0; j < CPW; ++j) {
            float m = -INFINITY;
#pragma unroll
            for (int dy = 0; dy < 3; ++dy)
#pragma unroll
                for (int dx = 0; dx < 3; ++dx)
                    m = fmaxf(m, pooled[warp][j][2 * oy + dy][2 * ox + dx]);
            out[(((size_t)k * NC + (c0 + j)) * 5 + oy) * 5 + ox] = m * 0.25f;
        }
    }
}

extern "C" void kernel_launch(void* const* d_in, const int* in_sizes, int n_in,
                              void* d_out, int out_size)
{
    const float* feat = (const float*)d_in[0];
    const float* rois = (const float*)d_in[1];
    float* out = (float*)d_out;

    const int K = in_sizes[1] / 5;  // 512 rois

    dim3 grid(K, NC / (WARPS * CPW));   // (512, 8)
    dim3 block(256);
    roialign_maxpool_kernel<<<grid, block>>>(feat, rois, out);
}